// round 12
// baseline (speedup 1.0000x reference)
#include <cuda_runtime.h>
#include <cuda_bf16.h>
#include <cstdint>

#define B_   2
#define CUR  1024
#define T_   2048
#define DM   1024
#define NH   16
#define DH   64
#define Z_   32
#define EXPC 0.1803368801111f   // 0.125 * log2(e)

// ---------------- device scratch ----------------
__device__ __align__(16) __nv_bfloat16 g_hb  [B_ * T_ * DM];      // concat(mem,x) bf16
__device__ __align__(16) __nv_bfloat16 g_Wb  [3 * DM * DM];       // [Wkv | Wq] bf16
__device__ __align__(16) __nv_bfloat16 g_Wfcb[DM * DM];
__device__ __align__(16) __nv_bfloat16 g_A3  [Z_ * CUR * 128];    // [q+u | shifted(q+v)]
__device__ __align__(16) __nv_bfloat16 g_B3  [Z_ * T_ * 128];     // [k | pe]
__device__ __align__(16) float         g_Vf  [Z_ * T_ * DH];      // V fp32 [z][j][d] coalesced
__device__ __align__(16) __nv_bfloat16 g_Sp  [(long)Z_ * CUR * T_]; // 128 MB e bf16
__device__ __align__(16) float         g_csp [Z_ * 8 * T_];       // partial colsums
__device__ __align__(16) __nv_bfloat16 g_B4v [Z_ * DH * T_];      // (V/colsum)^T bf16
__device__ __align__(16) __nv_bfloat16 g_Wp1 [B_ * CUR * DM];     // weighted bf16
__device__ __align__(16) float         g_y   [B_ * CUR * DM];

// ---------------- helpers ----------------
#define SWZ(off) ((off) ^ (((off) >> 3) & 0x70))

__device__ __forceinline__ uint32_t smem_u32(const void* p) {
    uint32_t a;
    asm("{ .reg .u64 t; cvta.to.shared.u64 t, %1; cvt.u32.u64 %0, t; }" : "=r"(a) : "l"(p));
    return a;
}
__device__ __forceinline__ void cp16(uint32_t d, const void* g) {
    asm volatile("cp.async.cg.shared.global [%0], [%1], 16;" :: "r"(d), "l"(g));
}
__device__ __forceinline__ void cp_commit() {
    asm volatile("cp.async.commit_group;" ::: "memory");
}
__device__ __forceinline__ void cp_wait1() {
    asm volatile("cp.async.wait_group 1;" ::: "memory");
}
__device__ __forceinline__ void ldsm4(uint32_t* r, uint32_t addr) {
    asm volatile("ldmatrix.sync.aligned.m8n8.x4.shared.b16 {%0,%1,%2,%3}, [%4];"
                 : "=r"(r[0]), "=r"(r[1]), "=r"(r[2]), "=r"(r[3]) : "r"(addr));
}
__device__ __forceinline__ void mma16816(float* c, const uint32_t* a, uint32_t b0, uint32_t b1) {
    asm volatile(
        "mma.sync.aligned.m16n8k16.row.col.f32.bf16.bf16.f32 "
        "{%0,%1,%2,%3}, {%4,%5,%6,%7}, {%8,%9}, {%0,%1,%2,%3};"
        : "+f"(c[0]), "+f"(c[1]), "+f"(c[2]), "+f"(c[3])
        : "r"(a[0]), "r"(a[1]), "r"(a[2]), "r"(a[3]), "r"(b0), "r"(b1));
}
__device__ __forceinline__ uint32_t pack_bf(float a, float b) {
    __nv_bfloat162 p = __floats2bfloat162_rn(a, b);
    return reinterpret_cast<uint32_t&>(p);
}
__device__ __forceinline__ float ex2(float x) {
    float y;
    asm("ex2.approx.f32 %0, %1;" : "=f"(y) : "f"(x));
    return y;
}

// ---------------- HMMA GEMM: C = A[M,K] @ B[N,K]^T, bf16 in / fp32 acc ----------------
// K-chunk = 128 bytes/row, ST-stage cp.async pipeline. Strides in BYTES.
// NOTE: ST=2 is only legal when NC<=2 (no in-loop prefetch happens then).
// EPI 2: e=ex2(acc*EXPC) -> g_Sp bf16 + deterministic partial colsums
// EPI 3: bf16 scatter -> g_Wp1   EPI 4: + residual + bias -> fp32
// EPI 6: merged kv+q epilogue: col<1024 k->g_B3; col<2048 v->g_Vf;
//        col>=2048 q -> A3 both halves (q+u own row, q+v rel-shifted row)
// zoff: z-batch offset (L2-residency halving of the logits->AV chain)
template <int EPI, int BM, int BN, int NT, int WTM, int WTN, int ST>
__global__ void __launch_bounds__(NT, 1) mma_gemm(
    const void* __restrict__ A, const void* __restrict__ Bm,
    float* __restrict__ Cf, __nv_bfloat16* __restrict__ Cb,
    int Kbytes, int Nout, long ldAb, long ldBb, long sAb, long sBb, int zoff,
    const float* __restrict__ add1, const float* __restrict__ add2)
{
    constexpr int WARPS   = NT / 32;
    constexpr int WARPS_N = BN / WTN;
    constexpr int WARPS_M = WARPS / WARPS_N;
    static_assert(WARPS_M * WTM == BM, "tile mismatch");
    constexpr int MFR = WTM / 16;
    constexpr int NFR = WTN / 8;
    constexpr int BFR = WTN / 16;
    constexpr int ASTG = BM * 128;
    constexpr int BSTG = BN * 128;
    constexpr int AIT = (BM * 8) / NT;
    constexpr int BIT = (BN * 8) / NT;

    const int m0 = blockIdx.y * BM, n0 = blockIdx.x * BN;
    // merged kernel: q columns only needed for x rows of the concat buffer
    if (EPI == 6 && n0 >= 2048 && !((m0 >> 10) & 1)) return;

    extern __shared__ __align__(1024) char smem[];
    const uint32_t sA_base = smem_u32(smem);
    const uint32_t sB_base = sA_base + ST * ASTG;

    const int tid = threadIdx.x;
    const int warp = tid >> 5, lane = tid & 31;
    const int wm = warp / WARPS_N, wn = warp % WARPS_N;

    const int z = blockIdx.z + zoff;
    const char* Ab = (const char*)A + (long)z * sAb;
    const char* Bb = (const char*)Bm + (long)z * sBb;
    const int NC = Kbytes >> 7;

    auto load_stage = [&](int c, int s) {
#pragma unroll
        for (int u = 0; u < AIT; u++) {
            int idx = tid + NT * u;
            int row = idx >> 3, ch = idx & 7;
            const void* g = Ab + (long)(m0 + row) * ldAb + c * 128 + ch * 16;
            cp16(sA_base + s * ASTG + SWZ(row * 128 + ch * 16), g);
        }
#pragma unroll
        for (int u = 0; u < BIT; u++) {
            int idx = tid + NT * u;
            int row = idx >> 3, ch = idx & 7;
            const void* g = Bb + (long)(n0 + row) * ldBb + c * 128 + ch * 16;
            cp16(sB_base + s * BSTG + SWZ(row * 128 + ch * 16), g);
        }
    };

    load_stage(0, 0); cp_commit();
    if (NC > 1) { load_stage(1, 1 % ST); }
    cp_commit();

    float acc[MFR][NFR][4];
#pragma unroll
    for (int i = 0; i < MFR; i++)
#pragma unroll
        for (int j = 0; j < NFR; j++)
#pragma unroll
            for (int e = 0; e < 4; e++) acc[i][j][e] = 0.f;

    const int lrow = ((lane >> 3) & 1) * 8 + (lane & 7);
    const int lcb  = (lane >> 4) * 16;

#pragma unroll 1
    for (int c = 0; c < NC; c++) {
        cp_wait1();
        __syncthreads();
        if (c + 2 < NC) load_stage(c + 2, (c + 2) % ST);
        cp_commit();

        const uint32_t ab = sA_base + (c % ST) * ASTG;
        const uint32_t bb = sB_base + (c % ST) * BSTG;
#pragma unroll
        for (int kk = 0; kk < 4; kk++) {
            uint32_t afr[MFR][4];
#pragma unroll
            for (int mi = 0; mi < MFR; mi++) {
                int row = wm * WTM + mi * 16 + lrow;
                ldsm4(afr[mi], ab + row * 128 + ((kk * 32 + lcb) ^ ((row & 7) << 4)));
            }
            uint32_t bfr[BFR][4];
#pragma unroll
            for (int nj = 0; nj < BFR; nj++) {
                int row = wn * WTN + nj * 16 + lrow;
                ldsm4(bfr[nj], bb + row * 128 + ((kk * 32 + lcb) ^ ((row & 7) << 4)));
            }
#pragma unroll
            for (int mi = 0; mi < MFR; mi++)
#pragma unroll
                for (int nf = 0; nf < NFR; nf++)
                    mma16816(acc[mi][nf], afr[mi], bfr[nf >> 1][nf & 1], bfr[nf >> 1][(nf & 1) + 2]);
        }
    }
    __syncthreads();

    // ---------------- epilogue ----------------
    const int trow = lane >> 2, tcol = (lane & 3) << 1;
    float p0[NFR], p1[NFR];
    if (EPI == 2) {
#pragma unroll
        for (int nf = 0; nf < NFR; nf++) { p0[nf] = 0.f; p1[nf] = 0.f; }
    }
#pragma unroll
    for (int mi = 0; mi < MFR; mi++) {
        const int r = m0 + wm * WTM + mi * 16 + trow;   // and r+8
#pragma unroll
        for (int nf = 0; nf < NFR; nf++) {
            const int col = n0 + wn * WTN + nf * 8 + tcol;
            float c0 = acc[mi][nf][0], c1 = acc[mi][nf][1];
            float c2 = acc[mi][nf][2], c3 = acc[mi][nf][3];
            if (EPI == 2) {
                float e0 = ex2(c0 * EXPC), e1 = ex2(c1 * EXPC);
                float e2 = ex2(c2 * EXPC), e3 = ex2(c3 * EXPC);
                __nv_bfloat16* base = g_Sp + ((long)z * CUR + r) * T_ + col;
                *reinterpret_cast<uint32_t*>(base)           = pack_bf(e0, e1);
                *reinterpret_cast<uint32_t*>(base + 8L * T_) = pack_bf(e2, e3);
                p0[nf] += e0 + e2;
                p1[nf] += e1 + e3;
            } else if (EPI == 3) {
                int b = z >> 4, h = z & 15;
                *reinterpret_cast<uint32_t*>(g_Wp1 + ((long)(b * CUR + r)) * DM + h * DH + col)     = pack_bf(c0, c1);
                *reinterpret_cast<uint32_t*>(g_Wp1 + ((long)(b * CUR + r + 8)) * DM + h * DH + col) = pack_bf(c2, c3);
            } else if (EPI == 4) {
                float2 x0 = *reinterpret_cast<const float2*>(add1 + (long)r * Nout + col);
                float2 x1 = *reinterpret_cast<const float2*>(add1 + (long)(r + 8) * Nout + col);
                float2 bb2 = *reinterpret_cast<const float2*>(add2 + col);
                *reinterpret_cast<float2*>(Cf + (long)r * Nout + col)       = make_float2(c0 + x0.x + bb2.x, c1 + x0.y + bb2.y);
                *reinterpret_cast<float2*>(Cf + (long)(r + 8) * Nout + col) = make_float2(c2 + x1.x + bb2.x, c3 + x1.y + bb2.y);
            } else if (EPI == 6) {
                int b0i = r >> 11, j0 = r & 2047;
                int b1i = (r + 8) >> 11, j1 = (r + 8) & 2047;
                if (col < DM) {                       // k -> g_B3 bf16
                    int h = col >> 6, d = col & 63;
                    *reinterpret_cast<uint32_t*>(g_B3 + ((long)((b0i * NH + h) * T_ + j0)) * 128 + d) = pack_bf(c0, c1);
                    *reinterpret_cast<uint32_t*>(g_B3 + ((long)((b1i * NH + h) * T_ + j1)) * 128 + d) = pack_bf(c2, c3);
                } else if (col < 2 * DM) {            // v -> g_Vf fp32 [z][j][d]
                    int nn = col - DM, h = nn >> 6, d = nn & 63;
                    *reinterpret_cast<float2*>(g_Vf + ((long)((b0i * NH + h) * T_ + j0)) * DH + d) = make_float2(c0, c1);
                    *reinterpret_cast<float2*>(g_Vf + ((long)((b1i * NH + h) * T_ + j1)) * DH + d) = make_float2(c2, c3);
                } else {                              // q -> A3 both halves (x rows only)
                    int cq = col - 2 * DM;
                    float2 uu = *reinterpret_cast<const float2*>(add1 + cq);
                    float2 vv = *reinterpret_cast<const float2*>(add2 + cq);
                    int h = cq >> 6, d = cq & 63;
#pragma unroll
                    for (int half = 0; half < 2; half++) {
                        int rr = r + half * 8;
                        float a0 = (half ? c2 : c0), a1 = (half ? c3 : c1);
                        int bq = rr >> 11, iq = (rr & 2047) - 1024;
                        *reinterpret_cast<uint32_t*>(
                            g_A3 + ((long)((bq * NH + h) * CUR + iq)) * 128 + d) = pack_bf(a0 + uu.x, a1 + uu.y);
                        int m1 = bq * 1025 + iq - 1;
                        if (m1 >= 0) {
                            int bb1 = m1 >> 10, i1 = m1 & 1023;
                            *reinterpret_cast<uint32_t*>(
                                g_A3 + ((long)((bb1 * NH + h) * CUR + i1)) * 128 + 64 + d) = pack_bf(a0 + vv.x, a1 + vv.y);
                        }
                    }
                }
            }
        }
    }

    if (EPI == 2) {
#pragma unroll
        for (int nf = 0; nf < NFR; nf++) {
#pragma unroll
            for (int o = 4; o < 32; o <<= 1) {
                p0[nf] += __shfl_xor_sync(0xffffffffu, p0[nf], o);
                p1[nf] += __shfl_xor_sync(0xffffffffu, p1[nf], o);
            }
        }
        float* scs = reinterpret_cast<float*>(smem);   // WARPS_M x BN floats
        if (lane < 4) {
#pragma unroll
            for (int nf = 0; nf < NFR; nf++) {
                scs[wm * BN + wn * WTN + nf * 8 + (lane & 3) * 2 + 0] = p0[nf];
                scs[wm * BN + wn * WTN + nf * 8 + (lane & 3) * 2 + 1] = p1[nf];
            }
        }
        __syncthreads();
        if (tid < BN) {
            float s = 0.f;
#pragma unroll
            for (int w = 0; w < WARPS_M; w++) s += scs[w * BN + tid];
            g_csp[((long)z * 8 + blockIdx.y) * T_ + n0 + tid] = s;
        }
    }
}

// ---------------- setup kernel: concat+convert, weights, pe, A3 zero-row ----------------
__global__ void conv_all(const float4* __restrict__ x, const float4* __restrict__ mem,
                         const float4* __restrict__ Wq, const float4* __restrict__ Wkv,
                         const float4* __restrict__ Wfc, const float* __restrict__ pos_emb) {
    int idx = blockIdx.x * 256 + threadIdx.x;
    if (idx < 1048576) {                 // concat(mem,x) -> g_hb
        int d4 = idx & 255, r = idx >> 8, t = r & 2047, b = r >> 11;
        float4 v = (t < 1024) ? mem[((b << 10) + t) * 256 + d4]
                              : x[((b << 10) + t - 1024) * 256 + d4];
        *reinterpret_cast<uint2*>(g_hb + (long)idx * 4) = make_uint2(pack_bf(v.x, v.y), pack_bf(v.z, v.w));
    } else if (idx < 2097152) {          // weights -> g_Wb ([Wkv|Wq]) and g_Wfcb
        int w = idx - 1048576;
        if (w < 786432) {
            float4 v = (w < 524288) ? Wkv[w] : Wq[w - 524288];
            *reinterpret_cast<uint2*>(g_Wb + (long)w * 4) = make_uint2(pack_bf(v.x, v.y), pack_bf(v.z, v.w));
        } else {
            float4 v = Wfc[w - 786432];
            *reinterpret_cast<uint2*>(g_Wfcb + (long)(w - 786432) * 4) = make_uint2(pack_bf(v.x, v.y), pack_bf(v.z, v.w));
        }
    } else if (idx < 6291456) {          // pe half of g_B3
        int w = idx - 2097152;
        int d = w & 63, j = (w >> 6) & 2047, z = w >> 17;
        int h = z & 15;
        g_B3[((long)(z * T_ + j)) * 128 + 64 + d] = __float2bfloat16(pos_emb[j * DM + (h << 6) + d]);
    } else {                             // zero unwritten A3 shifted row (b=0, i=1023)
        int w = idx - 6291456;           // < 1024
        int z2 = w >> 6, d2 = w & 63;
        g_A3[((long)(z2 * CUR + 1023)) * 128 + 64 + d2] = __float2bfloat16(0.f);
    }
}

// transpose + colsum-reduce + normalize + bf16: g_Vf[z][j][d] -> g_B4v[z][d][j]
__global__ void vprep2(int zoff) {
    __shared__ float tile[64][65];
    __shared__ float csr[64];
    int z = blockIdx.y + zoff, j0 = blockIdx.x * 64;
    int t = threadIdx.x;
#pragma unroll
    for (int p = 0; p < 16; p++) {
        int j = p * 4 + (t >> 6), d = t & 63;
        tile[j][d] = g_Vf[((long)(z * T_ + j0 + j)) * DH + d];
    }
    if (t < 64) {
        float s = 0.f;
#pragma unroll
        for (int my = 0; my < 8; my++) s += g_csp[((long)(z * 8 + my)) * T_ + j0 + t];
        csr[t] = s;
    }
    __syncthreads();
#pragma unroll
    for (int p = 0; p < 8; p++) {
        int d = p * 8 + (t >> 5), j2 = (t & 31) * 2;
        float v0 = tile[j2][d] / csr[j2];
        float v1 = tile[j2 + 1][d] / csr[j2 + 1];
        *reinterpret_cast<uint32_t*>(g_B4v + ((long)(z * DH + d)) * T_ + j0 + j2) = pack_bf(v0, v1);
    }
}

// ---------------- LayerNorm ----------------
__global__ void ln_kernel(const float* __restrict__ gamma,
                          const float* __restrict__ beta,
                          float* __restrict__ out) {
    int row = blockIdx.x;
    const float* yr = g_y + (long)row * DM;
    float v[4], s = 0.f, s2 = 0.f;
#pragma unroll
    for (int t = 0; t < 4; t++) {
        float x = yr[threadIdx.x + t * 256];
        v[t] = x; s += x; s2 += x * x;
    }
    __shared__ float sh[18];
#pragma unroll
    for (int o = 16; o > 0; o >>= 1) {
        s  += __shfl_down_sync(0xffffffffu, s,  o);
        s2 += __shfl_down_sync(0xffffffffu, s2, o);
    }
    int wid = threadIdx.x >> 5, lane = threadIdx.x & 31;
    if (lane == 0) { sh[wid] = s; sh[8 + wid] = s2; }
    __syncthreads();
    if (threadIdx.x == 0) {
        float ts = 0.f, ts2 = 0.f;
        for (int w = 0; w < 8; w++) { ts += sh[w]; ts2 += sh[8 + w]; }
        sh[16] = ts; sh[17] = ts2;
    }
    __syncthreads();
    float mu = sh[16] / DM, var = sh[17] / DM - mu * mu;
    float inv = rsqrtf(var + 1e-5f);
#pragma unroll
    for (int t = 0; t < 4; t++) {
        int c = threadIdx.x + t * 256;
        out[(long)row * DM + c] = (v[t] - mu) * inv * gamma[c] + beta[c];
    }
}

// ---------------- launch ----------------
extern "C" void kernel_launch(void* const* d_in, const int* in_sizes, int n_in,
                              void* d_out, int out_size) {
    const float* x       = (const float*)d_in[0];
    const float* pos_emb = (const float*)d_in[1];
    const float* u       = (const float*)d_in[2];
    const float* v       = (const float*)d_in[3];
    // d_in[4] = tgt_mask : all ones -> no-op
    const float* mem     = (const float*)d_in[5];
    const float* Wq      = (const float*)d_in[6];
    const float* Wkv     = (const float*)d_in[7];
    const float* Wfc     = (const float*)d_in[8];
    const float* bfc     = (const float*)d_in[9];
    const float* gamma   = (const float*)d_in[10];
    const float* beta    = (const float*)d_in[11];
    float* out           = (float*)d_out;

    __nv_bfloat16 *pHb, *pWb, *pWfcb, *pA3, *pB3, *pSp, *pB4v, *pWp1;
    float *pY;
    cudaGetSymbolAddress((void**)&pHb,   g_hb);
    cudaGetSymbolAddress((void**)&pWb,   g_Wb);
    cudaGetSymbolAddress((void**)&pWfcb, g_Wfcb);
    cudaGetSymbolAddress((void**)&pA3,   g_A3);
    cudaGetSymbolAddress((void**)&pB3,   g_B3);
    cudaGetSymbolAddress((void**)&pSp,   g_Sp);
    cudaGetSymbolAddress((void**)&pB4v,  g_B4v);
    cudaGetSymbolAddress((void**)&pWp1,  g_Wp1);
    cudaGetSymbolAddress((void**)&pY,    g_y);

    const int SM6  = 3 * (16384 + 16384);   // 98304
    const int SM2  = 2 * (16384 + 16384);   // 65536 (logits: NC=2, 2 stages)
    const int SM3  = 3 * (16384 + 8192);    // 73728 (AV: BM=128, BN=64)
    const int SM4  = 3 * (16384 + 16384);   // 98304
    cudaFuncSetAttribute(mma_gemm<6,128,128,128,64,64,3>, cudaFuncAttributeMaxDynamicSharedMemorySize, SM6);
    cudaFuncSetAttribute(mma_gemm<2,128,128,256,64,32,2>, cudaFuncAttributeMaxDynamicSharedMemorySize, SM2);
    cudaFuncSetAttribute(mma_gemm<3,128,64,256,32,32,3>,  cudaFuncAttributeMaxDynamicSharedMemorySize, SM3);
    cudaFuncSetAttribute(mma_gemm<4,128,128,128,64,64,3>, cudaFuncAttributeMaxDynamicSharedMemorySize, SM4);

    conv_all<<<24580, 256>>>((const float4*)x, (const float4*)mem,
                             (const float4*)Wq, (const float4*)Wkv, (const float4*)Wfc, pos_emb);

    // merged: [kv | q] = h @ [Wkv | Wq]^T -> k->g_B3, v->g_Vf, q->A3 (u/v fused)
    mma_gemm<6,128,128,128,64,64,3><<<dim3(24, 32, 1), 128, SM6>>>(
        pHb, pWb, nullptr, nullptr, 2048, 3072, 2048, 2048, 0, 0, 0, u, v);

    // logits -> e = exp(S/8) bf16 + partial colsums; AV consumes e while its
    // 64 MB half-slice is still L2-resident (two z-halves)
    for (int zh = 0; zh < 2; zh++) {
        int zoff = zh * 16;
        mma_gemm<2,128,128,256,64,32,2><<<dim3(16, 8, 16), 256, SM2>>>(
            pA3, pB3, nullptr, nullptr, 256, 2048, 256, 256,
            (long)CUR * 256, (long)T_ * 256, zoff, nullptr, nullptr);

        vprep2<<<dim3(32, 16), 256>>>(zoff);

        mma_gemm<3,128,64,256,32,32,3><<<dim3(1, 8, 16), 256, SM3>>>(
            pSp, pB4v, nullptr, nullptr, 4096, 64, 4096, 4096,
            (long)CUR * T_ * 2, (long)DH * T_ * 2, zoff, nullptr, nullptr);
    }

    // y = x + W @ Wfc^T + bfc
    mma_gemm<4,128,128,128,64,64,3><<<dim3(8, 16, 1), 128, SM4>>>(
        pWp1, pWfcb, pY, nullptr, 2048, 1024, 2048, 2048, 0, 0, 0, x, bfc);

    ln_kernel<<<B_ * CUR, 256>>>(gamma, beta, out);
}

// round 13
// speedup vs baseline: 1.1584x; 1.1584x over previous
#include <cuda_runtime.h>
#include <cuda_bf16.h>
#include <cstdint>

#define B_   2
#define CUR  1024
#define T_   2048
#define DM   1024
#define NH   16
#define DH   64
#define Z_   32
#define EXPC 0.1803368801111f   // 0.125 * log2(e)

// ---------------- device scratch ----------------
__device__ __align__(16) __nv_bfloat16 g_hb  [B_ * T_ * DM];      // concat(mem,x) bf16
__device__ __align__(16) __nv_bfloat16 g_Wb  [3 * DM * DM];       // [Wkv | Wq] bf16
__device__ __align__(16) __nv_bfloat16 g_Wfcb[DM * DM];
__device__ __align__(16) __nv_bfloat16 g_A3  [Z_ * CUR * 128];    // [q+u | shifted(q+v)]
__device__ __align__(16) __nv_bfloat16 g_B3  [Z_ * T_ * 128];     // [k | pe]
__device__ __align__(16) float         g_Vf  [Z_ * T_ * DH];      // V fp32 [z][j][d] coalesced
__device__ __align__(16) __nv_bfloat16 g_Sp  [(long)Z_ * CUR * T_]; // 128 MB e bf16
__device__ __align__(16) float         g_csp [Z_ * 8 * T_];       // partial colsums
__device__ __align__(16) __nv_bfloat16 g_B4v [Z_ * DH * T_];      // (V/colsum)^T bf16
__device__ __align__(16) __nv_bfloat16 g_Wp1 [B_ * CUR * DM];     // weighted bf16
__device__ __align__(16) float         g_y   [B_ * CUR * DM];

// ---------------- helpers ----------------
#define SWZ(off) ((off) ^ (((off) >> 3) & 0x70))

__device__ __forceinline__ uint32_t smem_u32(const void* p) {
    uint32_t a;
    asm("{ .reg .u64 t; cvta.to.shared.u64 t, %1; cvt.u32.u64 %0, t; }" : "=r"(a) : "l"(p));
    return a;
}
__device__ __forceinline__ void cp16(uint32_t d, const void* g) {
    asm volatile("cp.async.cg.shared.global [%0], [%1], 16;" :: "r"(d), "l"(g));
}
__device__ __forceinline__ void cp_commit() {
    asm volatile("cp.async.commit_group;" ::: "memory");
}
__device__ __forceinline__ void cp_wait1() {
    asm volatile("cp.async.wait_group 1;" ::: "memory");
}
__device__ __forceinline__ void ldsm4(uint32_t* r, uint32_t addr) {
    asm volatile("ldmatrix.sync.aligned.m8n8.x4.shared.b16 {%0,%1,%2,%3}, [%4];"
                 : "=r"(r[0]), "=r"(r[1]), "=r"(r[2]), "=r"(r[3]) : "r"(addr));
}
__device__ __forceinline__ void mma16816(float* c, const uint32_t* a, uint32_t b0, uint32_t b1) {
    asm volatile(
        "mma.sync.aligned.m16n8k16.row.col.f32.bf16.bf16.f32 "
        "{%0,%1,%2,%3}, {%4,%5,%6,%7}, {%8,%9}, {%0,%1,%2,%3};"
        : "+f"(c[0]), "+f"(c[1]), "+f"(c[2]), "+f"(c[3])
        : "r"(a[0]), "r"(a[1]), "r"(a[2]), "r"(a[3]), "r"(b0), "r"(b1));
}
__device__ __forceinline__ uint32_t pack_bf(float a, float b) {
    __nv_bfloat162 p = __floats2bfloat162_rn(a, b);
    return reinterpret_cast<uint32_t&>(p);
}
__device__ __forceinline__ float ex2(float x) {
    float y;
    asm("ex2.approx.f32 %0, %1;" : "=f"(y) : "f"(x));
    return y;
}

// ---------------- HMMA GEMM: C = A[M,K] @ B[N,K]^T, bf16 in / fp32 acc ----------------
// K-chunk = 128 bytes/row, ST-stage cp.async pipeline. Strides in BYTES.
// NOTE: ST=2 is only legal when NC<=2 (no in-loop prefetch happens then).
// EPI 2: e=ex2(acc*EXPC) -> g_Sp bf16 + deterministic partial colsums
// EPI 3: bf16 scatter -> g_Wp1   EPI 4: + residual + bias -> fp32
// EPI 6: merged kv+q epilogue: col<1024 k->g_B3; col<2048 v->g_Vf;
//        col>=2048 q -> A3 both halves (q+u own row, q+v rel-shifted row)
template <int EPI, int BM, int BN, int NT, int WTM, int WTN, int ST>
__global__ void __launch_bounds__(NT, 1) mma_gemm(
    const void* __restrict__ A, const void* __restrict__ Bm,
    float* __restrict__ Cf, __nv_bfloat16* __restrict__ Cb,
    int Kbytes, int Nout, long ldAb, long ldBb, long sAb, long sBb,
    const float* __restrict__ add1, const float* __restrict__ add2)
{
    constexpr int WARPS   = NT / 32;
    constexpr int WARPS_N = BN / WTN;
    constexpr int WARPS_M = WARPS / WARPS_N;
    static_assert(WARPS_M * WTM == BM, "tile mismatch");
    constexpr int MFR = WTM / 16;
    constexpr int NFR = WTN / 8;
    constexpr int BFR = WTN / 16;
    constexpr int ASTG = BM * 128;
    constexpr int BSTG = BN * 128;
    constexpr int AIT = (BM * 8) / NT;
    constexpr int BIT = (BN * 8) / NT;

    const int m0 = blockIdx.y * BM, n0 = blockIdx.x * BN;
    // merged kernel: q columns only needed for x rows of the concat buffer
    if (EPI == 6 && n0 >= 2048 && !((m0 >> 10) & 1)) return;

    extern __shared__ __align__(1024) char smem[];
    const uint32_t sA_base = smem_u32(smem);
    const uint32_t sB_base = sA_base + ST * ASTG;

    const int tid = threadIdx.x;
    const int warp = tid >> 5, lane = tid & 31;
    const int wm = warp / WARPS_N, wn = warp % WARPS_N;

    const int z = blockIdx.z;
    const char* Ab = (const char*)A + (long)z * sAb;
    const char* Bb = (const char*)Bm + (long)z * sBb;
    const int NC = Kbytes >> 7;

    auto load_stage = [&](int c, int s) {
#pragma unroll
        for (int u = 0; u < AIT; u++) {
            int idx = tid + NT * u;
            int row = idx >> 3, ch = idx & 7;
            const void* g = Ab + (long)(m0 + row) * ldAb + c * 128 + ch * 16;
            cp16(sA_base + s * ASTG + SWZ(row * 128 + ch * 16), g);
        }
#pragma unroll
        for (int u = 0; u < BIT; u++) {
            int idx = tid + NT * u;
            int row = idx >> 3, ch = idx & 7;
            const void* g = Bb + (long)(n0 + row) * ldBb + c * 128 + ch * 16;
            cp16(sB_base + s * BSTG + SWZ(row * 128 + ch * 16), g);
        }
    };

    load_stage(0, 0); cp_commit();
    if (NC > 1) { load_stage(1, 1 % ST); }
    cp_commit();

    float acc[MFR][NFR][4];
#pragma unroll
    for (int i = 0; i < MFR; i++)
#pragma unroll
        for (int j = 0; j < NFR; j++)
#pragma unroll
            for (int e = 0; e < 4; e++) acc[i][j][e] = 0.f;

    const int lrow = ((lane >> 3) & 1) * 8 + (lane & 7);
    const int lcb  = (lane >> 4) * 16;

#pragma unroll 1
    for (int c = 0; c < NC; c++) {
        cp_wait1();
        __syncthreads();
        if (c + 2 < NC) load_stage(c + 2, (c + 2) % ST);
        cp_commit();

        const uint32_t ab = sA_base + (c % ST) * ASTG;
        const uint32_t bb = sB_base + (c % ST) * BSTG;
#pragma unroll
        for (int kk = 0; kk < 4; kk++) {
            uint32_t afr[MFR][4];
#pragma unroll
            for (int mi = 0; mi < MFR; mi++) {
                int row = wm * WTM + mi * 16 + lrow;
                ldsm4(afr[mi], ab + row * 128 + ((kk * 32 + lcb) ^ ((row & 7) << 4)));
            }
            uint32_t bfr[BFR][4];
#pragma unroll
            for (int nj = 0; nj < BFR; nj++) {
                int row = wn * WTN + nj * 16 + lrow;
                ldsm4(bfr[nj], bb + row * 128 + ((kk * 32 + lcb) ^ ((row & 7) << 4)));
            }
#pragma unroll
            for (int mi = 0; mi < MFR; mi++)
#pragma unroll
                for (int nf = 0; nf < NFR; nf++)
                    mma16816(acc[mi][nf], afr[mi], bfr[nf >> 1][nf & 1], bfr[nf >> 1][(nf & 1) + 2]);
        }
    }
    __syncthreads();

    // ---------------- epilogue ----------------
    const int trow = lane >> 2, tcol = (lane & 3) << 1;
    float p0[NFR], p1[NFR];
    if (EPI == 2) {
#pragma unroll
        for (int nf = 0; nf < NFR; nf++) { p0[nf] = 0.f; p1[nf] = 0.f; }
    }
#pragma unroll
    for (int mi = 0; mi < MFR; mi++) {
        const int r = m0 + wm * WTM + mi * 16 + trow;   // and r+8
#pragma unroll
        for (int nf = 0; nf < NFR; nf++) {
            const int col = n0 + wn * WTN + nf * 8 + tcol;
            float c0 = acc[mi][nf][0], c1 = acc[mi][nf][1];
            float c2 = acc[mi][nf][2], c3 = acc[mi][nf][3];
            if (EPI == 2) {
                float e0 = ex2(c0 * EXPC), e1 = ex2(c1 * EXPC);
                float e2 = ex2(c2 * EXPC), e3 = ex2(c3 * EXPC);
                __nv_bfloat16* base = g_Sp + ((long)z * CUR + r) * T_ + col;
                *reinterpret_cast<uint32_t*>(base)           = pack_bf(e0, e1);
                *reinterpret_cast<uint32_t*>(base + 8L * T_) = pack_bf(e2, e3);
                p0[nf] += e0 + e2;
                p1[nf] += e1 + e3;
            } else if (EPI == 3) {
                int b = z >> 4, h = z & 15;
                *reinterpret_cast<uint32_t*>(g_Wp1 + ((long)(b * CUR + r)) * DM + h * DH + col)     = pack_bf(c0, c1);
                *reinterpret_cast<uint32_t*>(g_Wp1 + ((long)(b * CUR + r + 8)) * DM + h * DH + col) = pack_bf(c2, c3);
            } else if (EPI == 4) {
                float2 x0 = *reinterpret_cast<const float2*>(add1 + (long)r * Nout + col);
                float2 x1 = *reinterpret_cast<const float2*>(add1 + (long)(r + 8) * Nout + col);
                float2 bb2 = *reinterpret_cast<const float2*>(add2 + col);
                *reinterpret_cast<float2*>(Cf + (long)r * Nout + col)       = make_float2(c0 + x0.x + bb2.x, c1 + x0.y + bb2.y);
                *reinterpret_cast<float2*>(Cf + (long)(r + 8) * Nout + col) = make_float2(c2 + x1.x + bb2.x, c3 + x1.y + bb2.y);
            } else if (EPI == 6) {
                int b0i = r >> 11, j0 = r & 2047;
                int b1i = (r + 8) >> 11, j1 = (r + 8) & 2047;
                if (col < DM) {                       // k -> g_B3 bf16
                    int h = col >> 6, d = col & 63;
                    *reinterpret_cast<uint32_t*>(g_B3 + ((long)((b0i * NH + h) * T_ + j0)) * 128 + d) = pack_bf(c0, c1);
                    *reinterpret_cast<uint32_t*>(g_B3 + ((long)((b1i * NH + h) * T_ + j1)) * 128 + d) = pack_bf(c2, c3);
                } else if (col < 2 * DM) {            // v -> g_Vf fp32 [z][j][d]
                    int nn = col - DM, h = nn >> 6, d = nn & 63;
                    *reinterpret_cast<float2*>(g_Vf + ((long)((b0i * NH + h) * T_ + j0)) * DH + d) = make_float2(c0, c1);
                    *reinterpret_cast<float2*>(g_Vf + ((long)((b1i * NH + h) * T_ + j1)) * DH + d) = make_float2(c2, c3);
                } else {                              // q -> A3 both halves (x rows only)
                    int cq = col - 2 * DM;
                    float2 uu = *reinterpret_cast<const float2*>(add1 + cq);
                    float2 vv = *reinterpret_cast<const float2*>(add2 + cq);
                    int h = cq >> 6, d = cq & 63;
#pragma unroll
                    for (int half = 0; half < 2; half++) {
                        int rr = r + half * 8;
                        float a0 = (half ? c2 : c0), a1 = (half ? c3 : c1);
                        int bq = rr >> 11, iq = (rr & 2047) - 1024;
                        *reinterpret_cast<uint32_t*>(
                            g_A3 + ((long)((bq * NH + h) * CUR + iq)) * 128 + d) = pack_bf(a0 + uu.x, a1 + uu.y);
                        int m1 = bq * 1025 + iq - 1;
                        if (m1 >= 0) {
                            int bb1 = m1 >> 10, i1 = m1 & 1023;
                            *reinterpret_cast<uint32_t*>(
                                g_A3 + ((long)((bb1 * NH + h) * CUR + i1)) * 128 + 64 + d) = pack_bf(a0 + vv.x, a1 + vv.y);
                        }
                    }
                }
            }
        }
    }

    if (EPI == 2) {
#pragma unroll
        for (int nf = 0; nf < NFR; nf++) {
#pragma unroll
            for (int o = 4; o < 32; o <<= 1) {
                p0[nf] += __shfl_xor_sync(0xffffffffu, p0[nf], o);
                p1[nf] += __shfl_xor_sync(0xffffffffu, p1[nf], o);
            }
        }
        float* scs = reinterpret_cast<float*>(smem);   // WARPS_M x BN floats
        if (lane < 4) {
#pragma unroll
            for (int nf = 0; nf < NFR; nf++) {
                scs[wm * BN + wn * WTN + nf * 8 + (lane & 3) * 2 + 0] = p0[nf];
                scs[wm * BN + wn * WTN + nf * 8 + (lane & 3) * 2 + 1] = p1[nf];
            }
        }
        __syncthreads();
        if (tid < BN) {
            float s = 0.f;
#pragma unroll
            for (int w = 0; w < WARPS_M; w++) s += scs[w * BN + tid];
            g_csp[((long)z * 8 + blockIdx.y) * T_ + n0 + tid] = s;
        }
    }
}

// ---------------- setup kernel: concat+convert, weights, pe, A3 zero-row ----------------
__global__ void conv_all(const float4* __restrict__ x, const float4* __restrict__ mem,
                         const float4* __restrict__ Wq, const float4* __restrict__ Wkv,
                         const float4* __restrict__ Wfc, const float* __restrict__ pos_emb) {
    int idx = blockIdx.x * 256 + threadIdx.x;
    if (idx < 1048576) {                 // concat(mem,x) -> g_hb
        int d4 = idx & 255, r = idx >> 8, t = r & 2047, b = r >> 11;
        float4 v = (t < 1024) ? mem[((b << 10) + t) * 256 + d4]
                              : x[((b << 10) + t - 1024) * 256 + d4];
        *reinterpret_cast<uint2*>(g_hb + (long)idx * 4) = make_uint2(pack_bf(v.x, v.y), pack_bf(v.z, v.w));
    } else if (idx < 2097152) {          // weights -> g_Wb ([Wkv|Wq]) and g_Wfcb
        int w = idx - 1048576;
        if (w < 786432) {
            float4 v = (w < 524288) ? Wkv[w] : Wq[w - 524288];
            *reinterpret_cast<uint2*>(g_Wb + (long)w * 4) = make_uint2(pack_bf(v.x, v.y), pack_bf(v.z, v.w));
        } else {
            float4 v = Wfc[w - 786432];
            *reinterpret_cast<uint2*>(g_Wfcb + (long)(w - 786432) * 4) = make_uint2(pack_bf(v.x, v.y), pack_bf(v.z, v.w));
        }
    } else if (idx < 6291456) {          // pe half of g_B3
        int w = idx - 2097152;
        int d = w & 63, j = (w >> 6) & 2047, z = w >> 17;
        int h = z & 15;
        g_B3[((long)(z * T_ + j)) * 128 + 64 + d] = __float2bfloat16(pos_emb[j * DM + (h << 6) + d]);
    } else {                             // zero unwritten A3 shifted row (b=0, i=1023)
        int w = idx - 6291456;           // < 1024
        int z2 = w >> 6, d2 = w & 63;
        g_A3[((long)(z2 * CUR + 1023)) * 128 + 64 + d2] = __float2bfloat16(0.f);
    }
}

// transpose + colsum-reduce + normalize + bf16: g_Vf[z][j][d] -> g_B4v[z][d][j]
__global__ void vprep2() {
    __shared__ float tile[64][65];
    __shared__ float csr[64];
    int z = blockIdx.y, j0 = blockIdx.x * 64;
    int t = threadIdx.x;
#pragma unroll
    for (int p = 0; p < 16; p++) {
        int j = p * 4 + (t >> 6), d = t & 63;
        tile[j][d] = g_Vf[((long)(z * T_ + j0 + j)) * DH + d];
    }
    if (t < 64) {
        float s = 0.f;
#pragma unroll
        for (int my = 0; my < 8; my++) s += g_csp[((long)(z * 8 + my)) * T_ + j0 + t];
        csr[t] = s;
    }
    __syncthreads();
#pragma unroll
    for (int p = 0; p < 8; p++) {
        int d = p * 8 + (t >> 5), j2 = (t & 31) * 2;
        float v0 = tile[j2][d] / csr[j2];
        float v1 = tile[j2 + 1][d] / csr[j2 + 1];
        *reinterpret_cast<uint32_t*>(g_B4v + ((long)(z * DH + d)) * T_ + j0 + j2) = pack_bf(v0, v1);
    }
}

// ---------------- LayerNorm ----------------
__global__ void ln_kernel(const float* __restrict__ gamma,
                          const float* __restrict__ beta,
                          float* __restrict__ out) {
    int row = blockIdx.x;
    const float* yr = g_y + (long)row * DM;
    float v[4], s = 0.f, s2 = 0.f;
#pragma unroll
    for (int t = 0; t < 4; t++) {
        float x = yr[threadIdx.x + t * 256];
        v[t] = x; s += x; s2 += x * x;
    }
    __shared__ float sh[18];
#pragma unroll
    for (int o = 16; o > 0; o >>= 1) {
        s  += __shfl_down_sync(0xffffffffu, s,  o);
        s2 += __shfl_down_sync(0xffffffffu, s2, o);
    }
    int wid = threadIdx.x >> 5, lane = threadIdx.x & 31;
    if (lane == 0) { sh[wid] = s; sh[8 + wid] = s2; }
    __syncthreads();
    if (threadIdx.x == 0) {
        float ts = 0.f, ts2 = 0.f;
        for (int w = 0; w < 8; w++) { ts += sh[w]; ts2 += sh[8 + w]; }
        sh[16] = ts; sh[17] = ts2;
    }
    __syncthreads();
    float mu = sh[16] / DM, var = sh[17] / DM - mu * mu;
    float inv = rsqrtf(var + 1e-5f);
#pragma unroll
    for (int t = 0; t < 4; t++) {
        int c = threadIdx.x + t * 256;
        out[(long)row * DM + c] = (v[t] - mu) * inv * gamma[c] + beta[c];
    }
}

// ---------------- launch ----------------
extern "C" void kernel_launch(void* const* d_in, const int* in_sizes, int n_in,
                              void* d_out, int out_size) {
    const float* x       = (const float*)d_in[0];
    const float* pos_emb = (const float*)d_in[1];
    const float* u       = (const float*)d_in[2];
    const float* v       = (const float*)d_in[3];
    // d_in[4] = tgt_mask : all ones -> no-op
    const float* mem     = (const float*)d_in[5];
    const float* Wq      = (const float*)d_in[6];
    const float* Wkv     = (const float*)d_in[7];
    const float* Wfc     = (const float*)d_in[8];
    const float* bfc     = (const float*)d_in[9];
    const float* gamma   = (const float*)d_in[10];
    const float* beta    = (const float*)d_in[11];
    float* out           = (float*)d_out;

    __nv_bfloat16 *pHb, *pWb, *pWfcb, *pA3, *pB3, *pSp, *pB4v, *pWp1;
    float *pY;
    cudaGetSymbolAddress((void**)&pHb,   g_hb);
    cudaGetSymbolAddress((void**)&pWb,   g_Wb);
    cudaGetSymbolAddress((void**)&pWfcb, g_Wfcb);
    cudaGetSymbolAddress((void**)&pA3,   g_A3);
    cudaGetSymbolAddress((void**)&pB3,   g_B3);
    cudaGetSymbolAddress((void**)&pSp,   g_Sp);
    cudaGetSymbolAddress((void**)&pB4v,  g_B4v);
    cudaGetSymbolAddress((void**)&pWp1,  g_Wp1);
    cudaGetSymbolAddress((void**)&pY,    g_y);

    const int SM6  = 3 * (16384 + 16384);   // 98304
    const int SM2  = 2 * (16384 + 16384);   // 65536 (logits: NC=2, 2 stages)
    const int SM3  = 3 * (16384 + 8192);    // 73728 (AV: BM=128, BN=64)
    const int SM4  = 3 * (16384 + 16384);   // 98304
    cudaFuncSetAttribute(mma_gemm<6,128,128,128,64,64,3>, cudaFuncAttributeMaxDynamicSharedMemorySize, SM6);
    cudaFuncSetAttribute(mma_gemm<2,128,128,256,64,32,2>, cudaFuncAttributeMaxDynamicSharedMemorySize, SM2);
    cudaFuncSetAttribute(mma_gemm<3,128,64,256,32,32,3>,  cudaFuncAttributeMaxDynamicSharedMemorySize, SM3);
    cudaFuncSetAttribute(mma_gemm<4,128,128,128,64,64,3>, cudaFuncAttributeMaxDynamicSharedMemorySize, SM4);

    conv_all<<<24580, 256>>>((const float4*)x, (const float4*)mem,
                             (const float4*)Wq, (const float4*)Wkv, (const float4*)Wfc, pos_emb);

    // merged: [kv | q] = h @ [Wkv | Wq]^T -> k->g_B3, v->g_Vf, q->A3 (u/v fused)
    mma_gemm<6,128,128,128,64,64,3><<<dim3(24, 32, 1), 128, SM6>>>(
        pHb, pWb, nullptr, nullptr, 2048, 3072, 2048, 2048, 0, 0, u, v);

    // logits -> e = exp(S/8) bf16 + partial colsums (NC=2, 2-stage, 16 warps/SM)
    mma_gemm<2,128,128,256,64,32,2><<<dim3(16, 8, Z_), 256, SM2>>>(
        pA3, pB3, nullptr, nullptr, 256, 2048, 256, 256,
        (long)CUR * 256, (long)T_ * 256, nullptr, nullptr);

    vprep2<<<dim3(32, Z_), 256>>>();

    // weighted = e @ (V/colsum)^T  (bf16), BM=128 halves B re-reads
    mma_gemm<3,128,64,256,32,32,3><<<dim3(1, 8, Z_), 256, SM3>>>(
        pSp, pB4v, nullptr, nullptr, 4096, 64, 4096, 4096,
        (long)CUR * T_ * 2, (long)DH * T_ * 2, nullptr, nullptr);

    // y = x + W @ Wfc^T + bfc
    mma_gemm<4,128,128,128,64,64,3><<<dim3(8, 16, 1), 128, SM4>>>(
        pWp1, pWfcb, pY, nullptr, 2048, 1024, 2048, 2048, 0, 0, x, bfc);

    ln_kernel<<<B_ * CUR, 256>>>(gamma, beta, out);
}